// round 6
// baseline (speedup 1.0000x reference)
#include <cuda_runtime.h>
#include <cuda_bf16.h>

// Chamfer distance via uniform spatial grid, fully fused into ONE persistent
// kernel with software grid barriers. B=2, N=M=8192, C=3, coords ~U[0,1).
//
// Phases (separated by grid_sync):
//   1. count points per cell (counts pre-zeroed: static init on first launch,
//      re-zeroed during query phase of every launch -> replay-invariant)
//   2. per-set block scan (CTA s handles set s) -> ranges + cursors
//   3. scatter to cell-sorted float4 (xyz, ||p||^2) + original index
//   4. query: ring search, write dist to g_dist[original index]; also re-zero counts
//   5. fixed-order reduce -> per-CTA partials
//   6. CTA 0 finalizes scalar output
//
// Determinism: cell-internal order from atomics is a permutation; fminf over a
// permuted set is invariant; distances land at original indices; all sums are
// fixed-order -> bitwise deterministic output.

#define G        16
#define NC       (G * G * G)
#define B_MAX    4
#define NSETS_MAX (2 * B_MAX)
#define NPTS_MAX 8192
#define BLK      256
#define CPT      (NC / BLK)          // 16 cells per thread in scan
#define MAXGRID  1024

__device__ int    g_count [NSETS_MAX * NC];          // static-init zero
__device__ int2   g_range [NSETS_MAX * NC];
__device__ int    g_cursor[NSETS_MAX * NC];
__device__ float4 g_sorted[NSETS_MAX * NPTS_MAX];
__device__ int    g_sidx  [NSETS_MAX * NPTS_MAX];
__device__ float  g_dist  [NSETS_MAX * NPTS_MAX];
__device__ float  g_p0[MAXGRID], g_p1[MAXGRID];

__device__ unsigned int g_bar_count = 0;
__device__ unsigned int g_bar_gen   = 0;

__device__ __forceinline__ void grid_sync() {
    __threadfence();                 // release this thread's prior writes
    __syncthreads();
    if (threadIdx.x == 0) {
        const unsigned int gen = atomicAdd(&g_bar_gen, 0u);
        const unsigned int t   = atomicAdd(&g_bar_count, 1u);
        if (t == gridDim.x - 1) {
            atomicExch(&g_bar_count, 0u);
            __threadfence();
            atomicAdd(&g_bar_gen, 1u);
        } else {
            while (atomicAdd(&g_bar_gen, 0u) == gen) { __nanosleep(64); }
        }
    }
    __syncthreads();
    __threadfence();                 // acquire: flush L1 so remote writes visible
}

__device__ __forceinline__ int cell_of(float v) {
    int c = (int)(v * (float)G);
    return min(max(c, 0), G - 1);
}

__device__ __forceinline__ float block_sum(float v, float* red) {
#pragma unroll
    for (int o = 16; o > 0; o >>= 1)
        v += __shfl_xor_sync(0xffffffffu, v, o);
    if ((threadIdx.x & 31) == 0) red[threadIdx.x >> 5] = v;
    __syncthreads();
    float s = 0.f;
    if (threadIdx.x == 0) {
#pragma unroll
        for (int w = 0; w < BLK / 32; ++w) s += red[w];
    }
    __syncthreads();
    return s;   // valid in thread 0 only
}

__global__ __launch_bounds__(BLK)
void chamfer_fused_kernel(const float* __restrict__ pos,
                          const float* __restrict__ xhat,
                          float* __restrict__ out, int out_size,
                          int N, int M, int B) {
    const int nsets = 2 * B;
    const int maxP  = (N > M) ? N : M;
    const int gtid  = blockIdx.x * BLK + threadIdx.x;
    const int T     = gridDim.x * BLK;

    __shared__ int   sc[BLK];
    __shared__ float redf[BLK / 32];

    // ---------------- Phase 1: count ----------------
    for (int j = gtid; j < nsets * maxP; j += T) {
        const int sid   = j / maxP;
        const int i     = j - sid * maxP;
        const int cloud = sid / B;
        const int b     = sid % B;
        const int n     = cloud ? M : N;
        if (i < n) {
            const float* P = cloud ? xhat : pos;
            const float* p = P + ((size_t)b * n + i) * 3;
            const int cell = (cell_of(p[2]) * G + cell_of(p[1])) * G + cell_of(p[0]);
            atomicAdd(&g_count[sid * NC + cell], 1);
        }
    }
    grid_sync();

    // ---------------- Phase 2: scan (CTA s handles set s) ----------------
    if (blockIdx.x < nsets) {
        const int base = blockIdx.x * NC;
        const int tid  = threadIdx.x;
        int c[CPT];
        int tsum = 0;
#pragma unroll
        for (int j = 0; j < CPT; ++j) { c[j] = g_count[base + tid * CPT + j]; tsum += c[j]; }
        sc[tid] = tsum;
        __syncthreads();
        for (int off = 1; off < BLK; off <<= 1) {
            int v = (tid >= off) ? sc[tid - off] : 0;
            __syncthreads();
            sc[tid] += v;
            __syncthreads();
        }
        int run = sc[tid] - tsum;
#pragma unroll
        for (int j = 0; j < CPT; ++j) {
            g_range [base + tid * CPT + j] = make_int2(run, c[j]);
            g_cursor[base + tid * CPT + j] = run;
            run += c[j];
        }
    }
    grid_sync();

    // ---------------- Phase 3: scatter ----------------
    for (int j = gtid; j < nsets * maxP; j += T) {
        const int sid   = j / maxP;
        const int i     = j - sid * maxP;
        const int cloud = sid / B;
        const int b     = sid % B;
        const int n     = cloud ? M : N;
        if (i < n) {
            const float* P = cloud ? xhat : pos;
            const float* p = P + ((size_t)b * n + i) * 3;
            const float x = p[0], y = p[1], z = p[2];
            const int cell = (cell_of(z) * G + cell_of(y)) * G + cell_of(x);
            const int idx  = atomicAdd(&g_cursor[sid * NC + cell], 1);
            g_sorted[sid * NPTS_MAX + idx] = make_float4(x, y, z, x * x + y * y + z * z);
            g_sidx  [sid * NPTS_MAX + idx] = i;
        }
    }
    grid_sync();

    // ---------------- Phase 4: query (+ re-zero counts for next launch) ----
    for (int j = gtid; j < nsets * NC; j += T) g_count[j] = 0;

    for (int j = gtid; j < nsets * maxP; j += T) {
        const int yb  = j / maxP;
        const int i   = j - yb * maxP;
        const int dir = yb / B;
        const int b   = yb % B;
        const int nQ  = dir ? M : N;
        if (i >= nQ) continue;
        const int sid_q = dir * B + b;
        const int sid_t = (1 - dir) * B + b;

        const float4 qf = g_sorted[sid_q * NPTS_MAX + i];
        const int    oi = g_sidx  [sid_q * NPTS_MAX + i];
        const float m2x = -2.0f * qf.x;
        const float m2y = -2.0f * qf.y;
        const float m2z = -2.0f * qf.z;
        const float qn  = qf.w;
        const int cx = cell_of(qf.x), cy = cell_of(qf.y), cz = cell_of(qf.z);

        const int2*   __restrict__ range = g_range  + sid_t * NC;
        const float4* __restrict__ pts   = g_sorted + sid_t * NPTS_MAX;

        const float h = 1.0f / (float)G;
        float minAcc = 3.4e38f;
        int r = 1;

        while (true) {
            const int x0 = max(cx - r, 0), x1 = min(cx + r, G - 1);
            const int y0 = max(cy - r, 0), y1 = min(cy + r, G - 1);
            const int z0 = max(cz - r, 0), z1 = min(cz + r, G - 1);

            for (int z = z0; z <= z1; ++z) {
                const int dz = abs(z - cz);
                for (int y = y0; y <= y1; ++y) {
                    const int dyz = max(abs(y - cy), dz);
                    const int rowbase = (z * G + y) * G;
                    if (r > 1 && dyz < r) {
#pragma unroll
                        for (int t = 0; t < 2; ++t) {
                            const int x = (t == 0) ? (cx - r) : (cx + r);
                            if (x < 0 || x > G - 1) continue;
                            const int2 rg = range[rowbase + x];
                            for (int k = 0; k < rg.y; ++k) {
                                const float4 tt = pts[rg.x + k];
                                const float d = fmaf(m2x, tt.x,
                                                fmaf(m2y, tt.y,
                                                fmaf(m2z, tt.z, tt.w)));
                                minAcc = fminf(minAcc, d);
                            }
                        }
                    } else {
                        for (int x = x0; x <= x1; ++x) {
                            const int2 rg = range[rowbase + x];
                            for (int k = 0; k < rg.y; ++k) {
                                const float4 tt = pts[rg.x + k];
                                const float d = fmaf(m2x, tt.x,
                                                fmaf(m2y, tt.y,
                                                fmaf(m2z, tt.z, tt.w)));
                                minAcc = fminf(minAcc, d);
                            }
                        }
                    }
                }
            }

            float db = 3.4e38f;
            if (x0 > 0)     db = fminf(db, qf.x - (float)x0 * h);
            if (x1 < G - 1) db = fminf(db, (float)(x1 + 1) * h - qf.x);
            if (y0 > 0)     db = fminf(db, qf.y - (float)y0 * h);
            if (y1 < G - 1) db = fminf(db, (float)(y1 + 1) * h - qf.y);
            if (z0 > 0)     db = fminf(db, qf.z - (float)z0 * h);
            if (z1 < G - 1) db = fminf(db, (float)(z1 + 1) * h - qf.z);

            const bool full = (x0 == 0 && y0 == 0 && z0 == 0 &&
                               x1 == G - 1 && y1 == G - 1 && z1 == G - 1);
            if (full || (qn + minAcc) <= db * db) break;
            ++r;
        }

        g_dist[(size_t)yb * NPTS_MAX + oi] = fmaxf(qn + minAcc, 0.0f);
    }
    grid_sync();

    // ---------------- Phase 5: fixed-order reduce ----------------
    {
        float s0 = 0.f;
        for (int j = gtid; j < B * N; j += T)
            s0 += g_dist[(size_t)(j / N) * NPTS_MAX + (j % N)];
        float s1 = 0.f;
        for (int j = gtid; j < B * M; j += T)
            s1 += g_dist[(size_t)(B + j / M) * NPTS_MAX + (j % M)];

        const float b0 = block_sum(s0, redf);
        const float b1 = block_sum(s1, redf);
        if (threadIdx.x == 0) {
            g_p0[blockIdx.x] = b0;
            g_p1[blockIdx.x] = b1;
        }
    }
    grid_sync();

    // ---------------- Phase 6: finalize (CTA 0) ----------------
    if (blockIdx.x == 0) {
        float s0 = 0.f, s1 = 0.f;
        for (int i = threadIdx.x; i < (int)gridDim.x; i += BLK) {
            s0 += g_p0[i];
            s1 += g_p1[i];
        }
        const float t0 = block_sum(s0, redf);
        const float t1 = block_sum(s1, redf);
        if (threadIdx.x == 0) {
            const float rec = t0 / (float)((size_t)B * N) + t1 / (float)((size_t)B * M);
            for (int i = 0; i < out_size; ++i) out[i] = rec;   // (loss, rec_loss)
        }
    }
}

extern "C" void kernel_launch(void* const* d_in, const int* in_sizes, int n_in,
                              void* d_out, int out_size) {
    const float* pos  = (const float*)d_in[0];
    const float* xhat = (const float*)d_in[1];

    const int B = 2;
    const int N = in_sizes[0] / (B * 3);
    const int M = in_sizes[1] / (B * 3);

    int sms = 148;
    {
        int dev = 0;
        cudaGetDevice(&dev);
        int v = 0;
        if (cudaDeviceGetAttribute(&v, cudaDevAttrMultiProcessorCount, dev) == cudaSuccess && v > 0)
            sms = v;
    }
    if (sms > MAXGRID) sms = MAXGRID;

    // grid == #SMs, 256 threads, tiny smem -> all CTAs co-resident in wave 1,
    // so the software grid barrier cannot deadlock.
    chamfer_fused_kernel<<<sms, BLK>>>(pos, xhat, (float*)d_out, out_size, N, M, B);
}

// round 7
// speedup vs baseline: 1.2845x; 1.2845x over previous
#include <cuda_runtime.h>
#include <cuda_bf16.h>

// Chamfer distance via uniform spatial grid, ONE persistent kernel.
// B=2, N=M=8192, C=3, coords ~U[0,1).
//
// Phases (software grid barriers between):
//   1. count points per cell              (atomicAdd)
//   2. per-set block scan (CTA s = set s) -> (start,count) + cursors
//   3. scatter to cell-sorted float4 (xyz,||p||^2) + orig idx; re-zero counts
//   4. query: 3x3x3 ring as 9 CONTIGUOUS row-spans, 18 independent range loads
//      issued up front (high MLP), then stream points; rare ring expansion.
//      dist -> g_dist[orig idx]
//   5. fixed-order reduce -> per-CTA partials; last-arriving CTA finalizes.
//
// Determinism: cell-internal permutation from atomics is harmless (min is
// permutation-invariant); distances land at original indices; all sums are
// fixed-order -> bitwise deterministic output. Scratch state is restored
// (counts zeroed, done-counter reset) so graph replays are identical.

#define G        16
#define NC       (G * G * G)
#define B_MAX    4
#define NSETS_MAX (2 * B_MAX)
#define NPTS_MAX 8192
#define BLK      256
#define CPT      (NC / BLK)
#define MAXGRID  1024

__device__ int    g_count [NSETS_MAX * NC];          // static-init zero
__device__ int2   g_range [NSETS_MAX * NC];
__device__ int    g_cursor[NSETS_MAX * NC];
__device__ float4 g_sorted[NSETS_MAX * NPTS_MAX];
__device__ int    g_sidx  [NSETS_MAX * NPTS_MAX];
__device__ float  g_dist  [NSETS_MAX * NPTS_MAX];
__device__ float  g_p0[MAXGRID], g_p1[MAXGRID];

__device__ unsigned int g_bar_count = 0;
__device__ unsigned int g_bar_gen   = 0;
__device__ unsigned int g_done      = 0;

__device__ __forceinline__ void grid_sync() {
    __threadfence();
    __syncthreads();
    if (threadIdx.x == 0) {
        const unsigned int gen = *(volatile unsigned int*)&g_bar_gen;
        const unsigned int t   = atomicAdd(&g_bar_count, 1u);
        if (t == gridDim.x - 1) {
            g_bar_count = 0;
            __threadfence();
            atomicAdd(&g_bar_gen, 1u);
        } else {
            while (*(volatile unsigned int*)&g_bar_gen == gen) { __nanosleep(64); }
        }
    }
    __syncthreads();
    __threadfence();   // acquire: L1 invalidate so remote writes are visible
}

__device__ __forceinline__ int cell_of(float v) {
    int c = (int)(v * (float)G);
    return min(max(c, 0), G - 1);
}

__device__ __forceinline__ float block_sum(float v, float* red) {
#pragma unroll
    for (int o = 16; o > 0; o >>= 1)
        v += __shfl_xor_sync(0xffffffffu, v, o);
    if ((threadIdx.x & 31) == 0) red[threadIdx.x >> 5] = v;
    __syncthreads();
    float s = 0.f;
    if (threadIdx.x == 0) {
#pragma unroll
        for (int w = 0; w < BLK / 32; ++w) s += red[w];
    }
    __syncthreads();
    return s;   // valid in thread 0 only
}

__global__ __launch_bounds__(BLK)
void chamfer_fused_kernel(const float* __restrict__ pos,
                          const float* __restrict__ xhat,
                          float* __restrict__ out, int out_size,
                          int N, int M, int B) {
    const int nsets = 2 * B;
    const int maxP  = (N > M) ? N : M;
    const int gtid  = blockIdx.x * BLK + threadIdx.x;
    const int T     = gridDim.x * BLK;

    __shared__ int   sc[BLK];
    __shared__ float redf[BLK / 32];
    __shared__ bool  amLast;

    // ---------------- Phase 1: count ----------------
    for (int j = gtid; j < nsets * maxP; j += T) {
        const int sid   = j / maxP;
        const int i     = j - sid * maxP;
        const int cloud = sid / B;
        const int b     = sid % B;
        const int n     = cloud ? M : N;
        if (i < n) {
            const float* P = cloud ? xhat : pos;
            const float* p = P + ((size_t)b * n + i) * 3;
            const int cell = (cell_of(p[2]) * G + cell_of(p[1])) * G + cell_of(p[0]);
            atomicAdd(&g_count[sid * NC + cell], 1);
        }
    }
    grid_sync();

    // ---------------- Phase 2: scan (CTA s handles set s) ----------------
    if (blockIdx.x < nsets) {
        const int base = blockIdx.x * NC;
        const int tid  = threadIdx.x;
        int c[CPT];
        int tsum = 0;
#pragma unroll
        for (int j = 0; j < CPT; ++j) { c[j] = g_count[base + tid * CPT + j]; tsum += c[j]; }
        sc[tid] = tsum;
        __syncthreads();
        for (int off = 1; off < BLK; off <<= 1) {
            int v = (tid >= off) ? sc[tid - off] : 0;
            __syncthreads();
            sc[tid] += v;
            __syncthreads();
        }
        int run = sc[tid] - tsum;
#pragma unroll
        for (int j = 0; j < CPT; ++j) {
            g_range [base + tid * CPT + j] = make_int2(run, c[j]);
            g_cursor[base + tid * CPT + j] = run;
            run += c[j];
        }
    }
    grid_sync();

    // ---------------- Phase 3: scatter (+ re-zero counts) ----------------
    for (int j = gtid; j < nsets * NC; j += T) g_count[j] = 0;

    for (int j = gtid; j < nsets * maxP; j += T) {
        const int sid   = j / maxP;
        const int i     = j - sid * maxP;
        const int cloud = sid / B;
        const int b     = sid % B;
        const int n     = cloud ? M : N;
        if (i < n) {
            const float* P = cloud ? xhat : pos;
            const float* p = P + ((size_t)b * n + i) * 3;
            const float x = p[0], y = p[1], z = p[2];
            const int cell = (cell_of(z) * G + cell_of(y)) * G + cell_of(x);
            const int idx  = atomicAdd(&g_cursor[sid * NC + cell], 1);
            g_sorted[sid * NPTS_MAX + idx] = make_float4(x, y, z, x * x + y * y + z * z);
            g_sidx  [sid * NPTS_MAX + idx] = i;
        }
    }
    grid_sync();

    // ---------------- Phase 4: query ----------------
    const float h = 1.0f / (float)G;
    for (int j = gtid; j < nsets * maxP; j += T) {
        const int yb  = j / maxP;
        const int i   = j - yb * maxP;
        const int dir = yb / B;
        const int b   = yb % B;
        const int nQ  = dir ? M : N;
        if (i >= nQ) continue;
        const int sid_q = dir * B + b;
        const int sid_t = (1 - dir) * B + b;

        const float4 qf = g_sorted[sid_q * NPTS_MAX + i];
        const int    oi = g_sidx  [sid_q * NPTS_MAX + i];
        const float m2x = -2.0f * qf.x;
        const float m2y = -2.0f * qf.y;
        const float m2z = -2.0f * qf.z;
        const float qn  = qf.w;
        const int cx = cell_of(qf.x), cy = cell_of(qf.y), cz = cell_of(qf.z);

        const int2*   __restrict__ range = g_range  + sid_t * NC;
        const float4* __restrict__ pts   = g_sorted + sid_t * NPTS_MAX;

        // --- r = 1 fast path: 9 contiguous row spans, all range loads upfront
        const int x0 = max(cx - 1, 0), x1 = min(cx + 1, G - 1);
        const int y0 = max(cy - 1, 0), y1 = min(cy + 1, G - 1);
        const int z0 = max(cz - 1, 0), z1 = min(cz + 1, G - 1);

        int sLo[9], sHi[9];
#pragma unroll
        for (int s = 0; s < 9; ++s) {
            // clamped duplicates at borders are harmless for min
            const int z = min(max(cz + s / 3 - 1, 0), G - 1);
            const int y = min(max(cy + s % 3 - 1, 0), G - 1);
            const int rb = (z * G + y) * G;
            const int2 lo = range[rb + x0];
            const int2 hi = range[rb + x1];
            sLo[s] = lo.x;
            sHi[s] = hi.x + hi.y;
        }

        float minAcc = 3.4e38f;
#pragma unroll
        for (int s = 0; s < 9; ++s) {
            for (int k = sLo[s]; k < sHi[s]; ++k) {
                const float4 tt = pts[k];
                const float d = fmaf(m2x, tt.x,
                                fmaf(m2y, tt.y,
                                fmaf(m2z, tt.z, tt.w)));
                minAcc = fminf(minAcc, d);
            }
        }

        // termination bound for the r=1 box
        float db = 3.4e38f;
        if (x0 > 0)     db = fminf(db, qf.x - (float)x0 * h);
        if (x1 < G - 1) db = fminf(db, (float)(x1 + 1) * h - qf.x);
        if (y0 > 0)     db = fminf(db, qf.y - (float)y0 * h);
        if (y1 < G - 1) db = fminf(db, (float)(y1 + 1) * h - qf.y);
        if (z0 > 0)     db = fminf(db, qf.z - (float)z0 * h);
        if (z1 < G - 1) db = fminf(db, (float)(z1 + 1) * h - qf.z);

        bool full = (x0 == 0 && y0 == 0 && z0 == 0 &&
                     x1 == G - 1 && y1 == G - 1 && z1 == G - 1);

        if (!full && (qn + minAcc) > db * db) {
            // --- rare expansion: rescan full (2r+1)^3 box via row spans
            int r = 2;
            while (true) {
                const int ex0 = max(cx - r, 0), ex1 = min(cx + r, G - 1);
                const int ey0 = max(cy - r, 0), ey1 = min(cy + r, G - 1);
                const int ez0 = max(cz - r, 0), ez1 = min(cz + r, G - 1);
                minAcc = 3.4e38f;
                for (int z = ez0; z <= ez1; ++z)
                    for (int y = ey0; y <= ey1; ++y) {
                        const int rb = (z * G + y) * G;
                        const int2 lo = range[rb + ex0];
                        const int2 hi = range[rb + ex1];
                        for (int k = lo.x; k < hi.x + hi.y; ++k) {
                            const float4 tt = pts[k];
                            const float d = fmaf(m2x, tt.x,
                                            fmaf(m2y, tt.y,
                                            fmaf(m2z, tt.z, tt.w)));
                            minAcc = fminf(minAcc, d);
                        }
                    }
                float edb = 3.4e38f;
                if (ex0 > 0)     edb = fminf(edb, qf.x - (float)ex0 * h);
                if (ex1 < G - 1) edb = fminf(edb, (float)(ex1 + 1) * h - qf.x);
                if (ey0 > 0)     edb = fminf(edb, qf.y - (float)ey0 * h);
                if (ey1 < G - 1) edb = fminf(edb, (float)(ey1 + 1) * h - qf.y);
                if (ez0 > 0)     edb = fminf(edb, qf.z - (float)ez0 * h);
                if (ez1 < G - 1) edb = fminf(edb, (float)(ez1 + 1) * h - qf.z);
                const bool efull = (ex0 == 0 && ey0 == 0 && ez0 == 0 &&
                                    ex1 == G - 1 && ey1 == G - 1 && ez1 == G - 1);
                if (efull || (qn + minAcc) <= edb * edb) break;
                ++r;
            }
        }

        g_dist[(size_t)yb * NPTS_MAX + oi] = fmaxf(qn + minAcc, 0.0f);
    }
    grid_sync();

    // ---------------- Phase 5: fixed-order reduce + last-CTA finalize ------
    {
        float s0 = 0.f;
        for (int j = gtid; j < B * N; j += T)
            s0 += g_dist[(size_t)(j / N) * NPTS_MAX + (j % N)];
        float s1 = 0.f;
        for (int j = gtid; j < B * M; j += T)
            s1 += g_dist[(size_t)(B + j / M) * NPTS_MAX + (j % M)];

        const float b0 = block_sum(s0, redf);
        const float b1 = block_sum(s1, redf);
        if (threadIdx.x == 0) {
            g_p0[blockIdx.x] = b0;
            g_p1[blockIdx.x] = b1;
            __threadfence();
            amLast = (atomicAdd(&g_done, 1u) == gridDim.x - 1);
        }
        __syncthreads();
    }

    if (amLast) {
        __threadfence();   // invalidate L1 so other CTAs' partials are visible
        float s0 = 0.f, s1 = 0.f;
        for (int i = threadIdx.x; i < (int)gridDim.x; i += BLK) {
            s0 += g_p0[i];
            s1 += g_p1[i];
        }
        const float t0 = block_sum(s0, redf);
        const float t1 = block_sum(s1, redf);
        if (threadIdx.x == 0) {
            g_done = 0;   // reset for next graph replay
            const float rec = t0 / (float)((size_t)B * N) + t1 / (float)((size_t)B * M);
            for (int i = 0; i < out_size; ++i) out[i] = rec;   // (loss, rec_loss)
        }
    }
}

extern "C" void kernel_launch(void* const* d_in, const int* in_sizes, int n_in,
                              void* d_out, int out_size) {
    const float* pos  = (const float*)d_in[0];
    const float* xhat = (const float*)d_in[1];

    const int B = 2;
    const int N = in_sizes[0] / (B * 3);
    const int M = in_sizes[1] / (B * 3);

    int sms = 148;
    {
        int dev = 0;
        cudaGetDevice(&dev);
        int v = 0;
        if (cudaDeviceGetAttribute(&v, cudaDevAttrMultiProcessorCount, dev) == cudaSuccess && v > 0)
            sms = v;
    }
    int grid = 2 * sms;                    // 2 CTAs/SM, still wave-1 co-resident
    if (grid > MAXGRID) grid = MAXGRID;

    chamfer_fused_kernel<<<grid, BLK>>>(pos, xhat, (float*)d_out, out_size, N, M, B);
}